// round 14
// baseline (speedup 1.0000x reference)
#include <cuda_runtime.h>
#include <cstdint>

#define NN 50000
#define EE 400000
#define DD 256
#define GG 64
#define DOUT 16

// ---------------- static scratch ----------------
__device__ float    g_S0[NN * DD];
__device__ float    g_S1[NN * DD];
__device__ uint32_t g_WpH[3][128 * DD];   // W packed bf16-hi pairs: [k/2][n]
__device__ uint32_t g_WpL[3][128 * DD];   // W packed bf16-lo pairs
__device__ int      g_degi[NN];
__device__ float    g_dinv[NN];
__device__ int      g_rowptr[NN + 1];
__device__ int      g_cursor[NN];
__device__ uint2    g_csr[EE];            // {src, weight-bits}
__device__ float    g_pool[GG * DD];
__device__ float    g_cnt[GG];
__device__ int      g_flags[2];
__device__ int      g_work[4];            // work-stealing cursors (per layer)

// ---------------- bf16 split helpers ----------------
// hi = truncate x to bf16 (top 16 bits); lo = rn-bf16(x - hi).
__device__ __forceinline__ void split2_bf16(float x0, float x1,
                                            uint32_t& whi, uint32_t& wlo) {
    uint32_t b0 = __float_as_uint(x0), b1 = __float_as_uint(x1);
    whi = __byte_perm(b0, b1, 0x7632);             // {hi(x1), hi(x0)}
    float h0 = __uint_as_float(b0 & 0xFFFF0000u);
    float h1 = __uint_as_float(b1 & 0xFFFF0000u);
    float l0 = x0 - h0, l1 = x1 - h1;
    asm("cvt.rn.bf16x2.f32 %0, %1, %2;" : "=r"(wlo) : "f"(l1), "f"(l0));
}

__device__ __forceinline__ void mma16(float* c, const uint32_t* a, const uint32_t* b) {
    asm volatile(
        "mma.sync.aligned.m16n8k16.row.col.f32.bf16.bf16.f32 "
        "{%0,%1,%2,%3}, {%4,%5,%6,%7}, {%8,%9}, {%0,%1,%2,%3};"
        : "+f"(c[0]), "+f"(c[1]), "+f"(c[2]), "+f"(c[3])
        : "r"(a[0]), "r"(a[1]), "r"(a[2]), "r"(a[3]), "r"(b[0]), "r"(b[1]));
}

// ---------------- index dtype ----------------
__device__ __forceinline__ long long fetch_idx(const void* p, long long i, int is32) {
    if (is32) return (long long)((const int*)p)[i];
    return ((const long long*)p)[i];
}

__global__ void k_zero() {
    int i = blockIdx.x * blockDim.x + threadIdx.x;
    if (i < NN) g_degi[i] = 0;
    if (i < GG * DD) g_pool[i] = 0.f;
    if (i < GG) g_cnt[i] = 0.f;
    if (i < 2) g_flags[i] = 0;
    if (i < 4) g_work[i] = 0;
}

__global__ void k_detect2(const unsigned* __restrict__ ei, long long ei_words,
                          const unsigned* __restrict__ bt, long long bt_words) {
    long long i = 2ll * ((long long)blockIdx.x * blockDim.x + threadIdx.x) + 1;
    unsigned v0 = (i < ei_words) ? ei[i] : 0u;
    unsigned v1 = (i < bt_words) ? bt[i] : 0u;
#pragma unroll
    for (int o = 16; o > 0; o >>= 1) {
        v0 |= __shfl_xor_sync(0xffffffffu, v0, o);
        v1 |= __shfl_xor_sync(0xffffffffu, v1, o);
    }
    if ((threadIdx.x & 31) == 0) {
        if (v0) atomicOr(&g_flags[0], 1);
        if (v1) atomicOr(&g_flags[1], 1);
    }
}

// pack all three weight matrices once: WpH/WpL[k'][n] = bf16 pair (W[2k'][n], W[2k'+1][n])
__global__ void k_prepw(const float* __restrict__ W1, const float* __restrict__ W2,
                        const float* __restrict__ W3) {
    int idx = blockIdx.x * 256 + threadIdx.x;   // k'(128) x n(256)
    if (idx >= 128 * DD) return;
    int kp = idx >> 8, n = idx & 255;
    const float* Ws[3] = {W1, W2, W3};
#pragma unroll
    for (int l = 0; l < 3; l++) {
        float x0 = Ws[l][(2 * kp) * DD + n];
        float x1 = Ws[l][(2 * kp + 1) * DD + n];
        uint32_t h, lo;
        split2_bf16(x0, x1, h, lo);
        g_WpH[l][kp * DD + n] = h;
        g_WpL[l][kp * DD + n] = lo;
    }
}

__global__ void k_count(const void* __restrict__ ei, long long E) {
    long long e = (long long)blockIdx.x * blockDim.x + threadIdx.x;
    if (e >= E) return;
    int is32 = g_flags[0];
    long long d = fetch_idx(ei, E + e, is32);
    atomicAdd(&g_degi[d], 1);
}

__global__ void k_scan_dinv() {
    __shared__ int part[1024];
    const int CH = (NN + 1023) / 1024;
    int t = threadIdx.x;
    int beg = t * CH, end = min(beg + CH, NN);
    int s = 0;
    for (int i = beg; i < end; i++) {
        int d = g_degi[i];
        g_dinv[i] = rsqrtf((float)d + 1.0f);
        s += d;
    }
    part[t] = s;
    __syncthreads();
    for (int off = 1; off < 1024; off <<= 1) {
        int v = (t >= off) ? part[t - off] : 0;
        __syncthreads();
        part[t] += v;
        __syncthreads();
    }
    int excl = (t == 0) ? 0 : part[t - 1];
    for (int i = beg; i < end; i++) {
        g_rowptr[i] = excl;
        g_cursor[i] = excl;
        excl += g_degi[i];
    }
    if (t == 1023) g_rowptr[NN] = part[1023];
}

__global__ void k_fill(const void* __restrict__ ei, long long E) {
    long long e = (long long)blockIdx.x * blockDim.x + threadIdx.x;
    if (e >= E) return;
    int is32 = g_flags[0];
    int s = (int)fetch_idx(ei, e, is32);
    int d = (int)fetch_idx(ei, E + e, is32);
    int pos = atomicAdd(&g_cursor[d], 1);
    float w = g_dinv[s] * g_dinv[d];
    g_csr[pos] = make_uint2((uint32_t)s, __float_as_uint(w));
}

// ---------------- bf16x2-split tensor GEMM (R9 k_gemm6, unchanged) -------------
#define APAD 12    // (12g+t)%32 distinct across a warp
#define BPAD 136   // 136%32==8 -> (8t+g)%32 distinct
#define A_WORDS (2 * 2 * 128 * APAD)           // 6144
#define B_WORDS (2 * 2 * 8 * BPAD)             // 4352
#define GEMM_SMEM ((A_WORDS + B_WORDS) * 4)    // 41984 bytes

#define AS(b, h, r, k) sA[((((b) * 2 + (h)) * 128 + (r)) * APAD) + (k)]
#define BS(b, h, k, n) sB[((((b) * 2 + (h)) * 8 + (k)) * BPAD) + (n)]

__global__ __launch_bounds__(256, 2) void k_gemm6(const float* __restrict__ A,
                                                  const uint32_t* __restrict__ BH,
                                                  const uint32_t* __restrict__ BL,
                                                  float* __restrict__ C, int M) {
    extern __shared__ uint32_t smem_dyn[];
    uint32_t* sA = smem_dyn;
    uint32_t* sB = smem_dyn + A_WORDS;

    int tid = threadIdx.x, wid = tid >> 5, lane = tid & 31;
    int g = lane >> 2, t = lane & 3;
    int wm = wid & 1, wn = wid >> 1;       // 2(m) x 4(n); warp tile 64x32
    int bm = blockIdx.x * 128;
    int bn = blockIdx.y * 128;

    int a_row  = tid >> 1;                 // 0..127
    int a_half = tid & 1;                  // k 0-7 or 8-15 of the 16-chunk
    int b_kp   = tid >> 5;                 // packed-k row 0..7
    int b_col  = (tid & 31) * 4;           // 4 n-words

    long long a_base = (long long)(bm + a_row) * DD + a_half * 8;
    bool a_ok = (bm + a_row) < M;
    const float4 z4 = make_float4(0.f, 0.f, 0.f, 0.f);

    float acc[4][4][4];
#pragma unroll
    for (int i = 0; i < 4; i++)
#pragma unroll
        for (int j = 0; j < 4; j++)
#pragma unroll
            for (int q = 0; q < 4; q++) acc[i][j][q] = 0.f;

    // prologue: stage chunk 0 into buffer 0
    {
        float4 v0 = a_ok ? *(const float4*)(A + a_base)     : z4;
        float4 v1 = a_ok ? *(const float4*)(A + a_base + 4) : z4;
        uint4 h, l;
        split2_bf16(v0.x, v0.y, h.x, l.x);
        split2_bf16(v0.z, v0.w, h.y, l.y);
        split2_bf16(v1.x, v1.y, h.z, l.z);
        split2_bf16(v1.z, v1.w, h.w, l.w);
        *(uint4*)&AS(0, 0, a_row, a_half * 4) = h;
        *(uint4*)&AS(0, 1, a_row, a_half * 4) = l;
        uint4 bh4 = *(const uint4*)(BH + (long long)b_kp * DD + bn + b_col);
        uint4 bl4 = *(const uint4*)(BL + (long long)b_kp * DD + bn + b_col);
        *(uint4*)&BS(0, 0, b_kp, b_col) = bh4;
        *(uint4*)&BS(0, 1, b_kp, b_col) = bl4;
    }
    __syncthreads();

    const int NSTEP = DD / 16;   // 16
    for (int k0 = 0; k0 < NSTEP; k0++) {
        int cur = k0 & 1, nxt = cur ^ 1;
        bool more = (k0 + 1) < NSTEP;

        float4 v0 = z4, v1 = z4;
        uint4 pbh = {0, 0, 0, 0}, pbl = {0, 0, 0, 0};
        if (more) {
            int kb = (k0 + 1) * 16;
            v0 = a_ok ? *(const float4*)(A + a_base + kb)     : z4;
            v1 = a_ok ? *(const float4*)(A + a_base + kb + 4) : z4;
            int kp = (k0 + 1) * 8 + b_kp;
            pbh = *(const uint4*)(BH + (long long)kp * DD + bn + b_col);
            pbl = *(const uint4*)(BL + (long long)kp * DD + bn + b_col);
        }

        uint32_t bh[4][2], bl[4][2];
#pragma unroll
        for (int j = 0; j < 4; j++) {
            int n = wn * 32 + 8 * j + g;
            bh[j][0] = BS(cur, 0, t, n);     bh[j][1] = BS(cur, 0, t + 4, n);
            bl[j][0] = BS(cur, 1, t, n);     bl[j][1] = BS(cur, 1, t + 4, n);
        }
#pragma unroll
        for (int i = 0; i < 4; i++) {
            int r = wm * 64 + i * 16;
            uint32_t ah[4], al[4];
            ah[0] = AS(cur, 0, r + g, t);      ah[1] = AS(cur, 0, r + g + 8, t);
            ah[2] = AS(cur, 0, r + g, t + 4);  ah[3] = AS(cur, 0, r + g + 8, t + 4);
            al[0] = AS(cur, 1, r + g, t);      al[1] = AS(cur, 1, r + g + 8, t);
            al[2] = AS(cur, 1, r + g, t + 4);  al[3] = AS(cur, 1, r + g + 8, t + 4);
#pragma unroll
            for (int j = 0; j < 4; j++) {
                mma16(acc[i][j], ah, bh[j]);
                mma16(acc[i][j], ah, bl[j]);
                mma16(acc[i][j], al, bh[j]);
            }
        }

        if (more) {
            uint4 h, l;
            split2_bf16(v0.x, v0.y, h.x, l.x);
            split2_bf16(v0.z, v0.w, h.y, l.y);
            split2_bf16(v1.x, v1.y, h.z, l.z);
            split2_bf16(v1.z, v1.w, h.w, l.w);
            *(uint4*)&AS(nxt, 0, a_row, a_half * 4) = h;
            *(uint4*)&AS(nxt, 1, a_row, a_half * 4) = l;
            *(uint4*)&BS(nxt, 0, b_kp, b_col) = pbh;
            *(uint4*)&BS(nxt, 1, b_kp, b_col) = pbl;
        }
        __syncthreads();
    }

#pragma unroll
    for (int i = 0; i < 4; i++)
#pragma unroll
        for (int j = 0; j < 4; j++) {
            int row0 = bm + wm * 64 + i * 16 + g;
            int col  = bn + wn * 32 + 8 * j + 2 * t;
            if (row0 < M) {
                float2 v = {acc[i][j][0], acc[i][j][1]};
                *(float2*)(C + (long long)row0 * DD + col) = v;
            }
            int row1 = row0 + 8;
            if (row1 < M) {
                float2 v = {acc[i][j][2], acc[i][j][3]};
                *(float2*)(C + (long long)row1 * DD + col) = v;
            }
        }
}

// ------ fused aggregate, work-stealing: warp pops chunks of 4 nodes ------------
#define AGG_CHUNK 4
#define AGG_BLOCKS 888

__global__ __launch_bounds__(256) void k_aggregate(const float* __restrict__ tmp,
                                                   float* __restrict__ out,
                                                   const float* __restrict__ bias,
                                                   int slot) {
    int lane = threadIdx.x & 31;
    float4 b0 = ((const float4*)bias)[lane];
    float4 b1 = ((const float4*)bias)[lane + 32];

    for (;;) {
        int base;
        if (lane == 0) base = atomicAdd(&g_work[slot], AGG_CHUNK);
        base = __shfl_sync(0xffffffffu, base, 0);
        if (base >= NN) break;
        int nend = min(base + AGG_CHUNK, NN);

        for (int node = base; node < nend; node++) {
            float di = g_dinv[node];
            float ws = di * di;
            const float4* r = (const float4*)(tmp + (long long)node * DD);
            float4 v0 = r[lane], v1 = r[lane + 32];
            float4 a0 = {v0.x * ws, v0.y * ws, v0.z * ws, v0.w * ws};
            float4 a1 = {v1.x * ws, v1.y * ws, v1.z * ws, v1.w * ws};

            int p = g_rowptr[node], pe = g_rowptr[node + 1];
            for (; p + 4 <= pe; p += 4) {
                uint2 e0 = g_csr[p],     e1 = g_csr[p + 1];
                uint2 e2 = g_csr[p + 2], e3 = g_csr[p + 3];
                const float4* r0 = (const float4*)(tmp + (long long)e0.x * DD);
                const float4* r1 = (const float4*)(tmp + (long long)e1.x * DD);
                const float4* r2 = (const float4*)(tmp + (long long)e2.x * DD);
                const float4* r3 = (const float4*)(tmp + (long long)e3.x * DD);
                float4 u00 = r0[lane], u01 = r0[lane + 32];
                float4 u10 = r1[lane], u11 = r1[lane + 32];
                float4 u20 = r2[lane], u21 = r2[lane + 32];
                float4 u30 = r3[lane], u31 = r3[lane + 32];
                float w0 = __uint_as_float(e0.y), w1 = __uint_as_float(e1.y);
                float w2 = __uint_as_float(e2.y), w3 = __uint_as_float(e3.y);
                a0.x += w0 * u00.x + w1 * u10.x + w2 * u20.x + w3 * u30.x;
                a0.y += w0 * u00.y + w1 * u10.y + w2 * u20.y + w3 * u30.y;
                a0.z += w0 * u00.z + w1 * u10.z + w2 * u20.z + w3 * u30.z;
                a0.w += w0 * u00.w + w1 * u10.w + w2 * u20.w + w3 * u30.w;
                a1.x += w0 * u01.x + w1 * u11.x + w2 * u21.x + w3 * u31.x;
                a1.y += w0 * u01.y + w1 * u11.y + w2 * u21.y + w3 * u31.y;
                a1.z += w0 * u01.z + w1 * u11.z + w2 * u21.z + w3 * u31.z;
                a1.w += w0 * u01.w + w1 * u11.w + w2 * u21.w + w3 * u31.w;
            }
            for (; p < pe; ++p) {
                uint2 e = g_csr[p];
                float w = __uint_as_float(e.y);
                const float4* rs = (const float4*)(tmp + (long long)e.x * DD);
                float4 u0 = rs[lane], u1 = rs[lane + 32];
                a0.x += w * u0.x; a0.y += w * u0.y; a0.z += w * u0.z; a0.w += w * u0.w;
                a1.x += w * u1.x; a1.y += w * u1.y; a1.z += w * u1.z; a1.w += w * u1.w;
            }

            float4 o0, o1;
            o0.x = fmaxf(a0.x + b0.x, 0.f); o0.y = fmaxf(a0.y + b0.y, 0.f);
            o0.z = fmaxf(a0.z + b0.z, 0.f); o0.w = fmaxf(a0.w + b0.w, 0.f);
            o1.x = fmaxf(a1.x + b1.x, 0.f); o1.y = fmaxf(a1.y + b1.y, 0.f);
            o1.z = fmaxf(a1.z + b1.z, 0.f); o1.w = fmaxf(a1.w + b1.w, 0.f);

            float4* o = (float4*)(out + (long long)node * DD);
            o[lane] = o0;
            o[lane + 32] = o1;
        }
    }
}

// ---------------- pool (batch sorted) + fc ----------------
__global__ void k_pool2(const float* __restrict__ h, const void* __restrict__ batch) {
    int col = threadIdx.x;
    int n0 = blockIdx.x * 128;
    int n1 = min(n0 + 128, NN);
    int is32 = g_flags[1];
    int cur = (int)fetch_idx(batch, n0, is32);
    float acc = 0.f;
    int cnt = 0;
    for (int n = n0; n < n1; n++) {
        int gid = (int)fetch_idx(batch, n, is32);
        if (gid != cur) {
            atomicAdd(&g_pool[cur * DD + col], acc);
            if (col == 0) atomicAdd(&g_cnt[cur], (float)cnt);
            acc = 0.f; cnt = 0; cur = gid;
        }
        acc += h[(long long)n * DD + col];
        cnt++;
    }
    atomicAdd(&g_pool[cur * DD + col], acc);
    if (col == 0) atomicAdd(&g_cnt[cur], (float)cnt);
}

__global__ void k_fc(const float* __restrict__ Wfc, const float* __restrict__ bfc,
                     float* __restrict__ out) {
    int tt = blockIdx.x * blockDim.x + threadIdx.x;
    if (tt >= GG * DOUT) return;
    int g = tt >> 4, o = tt & 15;
    float inv = 1.0f / fmaxf(g_cnt[g], 1.0f);
    float acc = 0.f;
#pragma unroll 8
    for (int k = 0; k < DD; k++) acc += g_pool[g * DD + k] * Wfc[k * DOUT + o];
    out[tt] = acc * inv + bfc[o];
}

// ---------------- launch ----------------
extern "C" void kernel_launch(void* const* d_in, const int* in_sizes, int n_in,
                              void* d_out, int out_size) {
    const float* x     = (const float*)d_in[0];
    const void*  ei    = d_in[1];
    const void*  batch = d_in[2];
    const float* W1 = (const float*)d_in[3];  const float* b1 = (const float*)d_in[4];
    const float* W2 = (const float*)d_in[5];  const float* b2 = (const float*)d_in[6];
    const float* W3 = (const float*)d_in[7];  const float* b3 = (const float*)d_in[8];
    const float* Wfc = (const float*)d_in[9]; const float* bfc = (const float*)d_in[10];
    float* out = (float*)d_out;

    long long E = in_sizes[1] / 2;

    float *S0, *S1;
    uint32_t *WpH, *WpL;
    cudaGetSymbolAddress((void**)&S0, g_S0);
    cudaGetSymbolAddress((void**)&S1, g_S1);
    cudaGetSymbolAddress((void**)&WpH, g_WpH);
    cudaGetSymbolAddress((void**)&WpL, g_WpL);

    cudaFuncSetAttribute(k_gemm6, cudaFuncAttributeMaxDynamicSharedMemorySize,
                         GEMM_SMEM);

    dim3 gemm_grid((NN + 127) / 128, 2);
    const float* bs[3] = {b1, b2, b3};

    // launch order: GEMM is launch #4 -> gets the ncu -s window
    k_zero<<<(NN + 255) / 256, 256>>>();                                       // 1
    k_detect2<<<(int)((in_sizes[1] / 2 + 255) / 256), 256>>>(
        (const unsigned*)ei, (long long)in_sizes[1],
        (const unsigned*)batch, (long long)in_sizes[2]);                       // 2
    k_prepw<<<128 * DD / 256, 256>>>(W1, W2, W3);                              // 3
    k_gemm6<<<gemm_grid, 256, GEMM_SMEM>>>(x, WpH, WpL, S0, NN);               // 4 (profiled)
    k_count<<<(int)((E + 255) / 256), 256>>>(ei, E);                           // 5
    k_scan_dinv<<<1, 1024>>>();                                                // 6
    k_fill<<<(int)((E + 255) / 256), 256>>>(ei, E);                            // 7
    k_aggregate<<<AGG_BLOCKS, 256>>>(S0, S1, bs[0], 0);                        // 8

    const float* in = S1;
    for (int l = 1; l < 3; l++) {
        k_gemm6<<<gemm_grid, 256, GEMM_SMEM>>>(in, WpH + (size_t)l * 128 * DD,
                                               WpL + (size_t)l * 128 * DD, S0, NN);
        k_aggregate<<<AGG_BLOCKS, 256>>>(S0, S1, bs[l], l);
        in = S1;
    }

    k_pool2<<<(NN + 127) / 128, 256>>>(S1, batch);
    k_fc<<<(GG * DOUT + 255) / 256, 256>>>(Wfc, bfc, out);
}

// round 15
// speedup vs baseline: 1.0413x; 1.0413x over previous
#include <cuda_runtime.h>
#include <cstdint>

#define NN 50000
#define EE 400000
#define DD 256
#define GG 64
#define DOUT 16

// ---------------- static scratch ----------------
__device__ float    g_S0[NN * DD];
__device__ float    g_S1[NN * DD];
__device__ uint32_t g_WpH[3][128 * DD];   // W packed bf16-hi pairs: [k/2][n]
__device__ uint32_t g_WpL[3][128 * DD];   // W packed bf16-lo pairs
__device__ int      g_degi[NN];
__device__ float    g_dinv[NN];
__device__ int      g_rowptr[NN + 1];
__device__ int      g_cursor[NN];
__device__ uint2    g_csr[EE];            // {src, weight-bits}
__device__ float    g_pool[GG * DD];
__device__ float    g_cnt[GG];
__device__ int      g_flags[2];           // zero-init at load; reset by k_fc each call

// ---------------- bf16 split helpers ----------------
__device__ __forceinline__ void split2_bf16(float x0, float x1,
                                            uint32_t& whi, uint32_t& wlo) {
    uint32_t b0 = __float_as_uint(x0), b1 = __float_as_uint(x1);
    whi = __byte_perm(b0, b1, 0x7632);             // {hi(x1), hi(x0)}
    float h0 = __uint_as_float(b0 & 0xFFFF0000u);
    float h1 = __uint_as_float(b1 & 0xFFFF0000u);
    float l0 = x0 - h0, l1 = x1 - h1;
    asm("cvt.rn.bf16x2.f32 %0, %1, %2;" : "=r"(wlo) : "f"(l1), "f"(l0));
}

__device__ __forceinline__ void mma16(float* c, const uint32_t* a, const uint32_t* b) {
    asm volatile(
        "mma.sync.aligned.m16n8k16.row.col.f32.bf16.bf16.f32 "
        "{%0,%1,%2,%3}, {%4,%5,%6,%7}, {%8,%9}, {%0,%1,%2,%3};"
        : "+f"(c[0]), "+f"(c[1]), "+f"(c[2]), "+f"(c[3])
        : "r"(a[0]), "r"(a[1]), "r"(a[2]), "r"(a[3]), "r"(b[0]), "r"(b[1]));
}

// ---------------- index dtype ----------------
__device__ __forceinline__ long long fetch_idx(const void* p, long long i, int is32) {
    if (is32) return (long long)((const int*)p)[i];
    return ((const long long*)p)[i];
}

// ---------------- launch 1: fused zero + detect + weight-pack ------------------
// blocks [0,128): prepw; [128,388): zero degi/pool/cnt; [388, 388+ndet): detect.
// g_flags is NOT zeroed here (raced by detect's atomicOr) — it starts 0 at module
// load and is reset to 0 by k_fc at the end of every call.
#define INIT_PREPW_BLKS 128
#define INIT_ZERO_BLKS  260
__global__ void k_init(const float* __restrict__ W1, const float* __restrict__ W2,
                       const float* __restrict__ W3,
                       const unsigned* __restrict__ ei, long long ei_words,
                       const unsigned* __restrict__ bt, long long bt_words) {
    int b = blockIdx.x;
    if (b < INIT_PREPW_BLKS) {
        int idx = b * 256 + threadIdx.x;          // k'(128) x n(256)
        int kp = idx >> 8, n = idx & 255;
        const float* Ws[3] = {W1, W2, W3};
#pragma unroll
        for (int l = 0; l < 3; l++) {
            float x0 = Ws[l][(2 * kp) * DD + n];
            float x1 = Ws[l][(2 * kp + 1) * DD + n];
            uint32_t h, lo;
            split2_bf16(x0, x1, h, lo);
            g_WpH[l][kp * DD + n] = h;
            g_WpL[l][kp * DD + n] = lo;
        }
        return;
    }
    if (b < INIT_PREPW_BLKS + INIT_ZERO_BLKS) {
        int i = (b - INIT_PREPW_BLKS) * 256 + threadIdx.x;
        if (i < NN) g_degi[i] = 0;
        int j = i - NN;
        if (j >= 0 && j < GG * DD) g_pool[j] = 0.f;
        int k = j - GG * DD;
        if (k >= 0 && k < GG) g_cnt[k] = 0.f;
        return;
    }
    // detect: OR all odd 32-bit words; int64 buffers (values < 2^31) give 0.
    long long base = (long long)(b - INIT_PREPW_BLKS - INIT_ZERO_BLKS) * 256 + threadIdx.x;
    long long i = 2 * base + 1;
    unsigned v0 = (i < ei_words) ? ei[i] : 0u;
    unsigned v1 = (i < bt_words) ? bt[i] : 0u;
#pragma unroll
    for (int o = 16; o > 0; o >>= 1) {
        v0 |= __shfl_xor_sync(0xffffffffu, v0, o);
        v1 |= __shfl_xor_sync(0xffffffffu, v1, o);
    }
    if ((threadIdx.x & 31) == 0) {
        if (v0) atomicOr(&g_flags[0], 1);
        if (v1) atomicOr(&g_flags[1], 1);
    }
}

__global__ void k_count(const void* __restrict__ ei, long long E) {
    long long e = (long long)blockIdx.x * blockDim.x + threadIdx.x;
    if (e >= E) return;
    int is32 = g_flags[0];
    long long d = fetch_idx(ei, E + e, is32);
    atomicAdd(&g_degi[d], 1);
}

__global__ void k_scan_dinv() {
    __shared__ int part[1024];
    const int CH = (NN + 1023) / 1024;
    int t = threadIdx.x;
    int beg = t * CH, end = min(beg + CH, NN);
    int s = 0;
    for (int i = beg; i < end; i++) {
        int d = g_degi[i];
        g_dinv[i] = rsqrtf((float)d + 1.0f);
        s += d;
    }
    part[t] = s;
    __syncthreads();
    for (int off = 1; off < 1024; off <<= 1) {
        int v = (t >= off) ? part[t - off] : 0;
        __syncthreads();
        part[t] += v;
        __syncthreads();
    }
    int excl = (t == 0) ? 0 : part[t - 1];
    for (int i = beg; i < end; i++) {
        g_rowptr[i] = excl;
        g_cursor[i] = excl;
        excl += g_degi[i];
    }
    if (t == 1023) g_rowptr[NN] = part[1023];
}

__global__ void k_fill(const void* __restrict__ ei, long long E) {
    long long e = (long long)blockIdx.x * blockDim.x + threadIdx.x;
    if (e >= E) return;
    int is32 = g_flags[0];
    int s = (int)fetch_idx(ei, e, is32);
    int d = (int)fetch_idx(ei, E + e, is32);
    int pos = atomicAdd(&g_cursor[d], 1);
    float w = g_dinv[s] * g_dinv[d];
    g_csr[pos] = make_uint2((uint32_t)s, __float_as_uint(w));
}

// ---------------- bf16x2-split tensor GEMM (R9/R12 form, unchanged) ------------
#define APAD 12
#define BPAD 136
#define A_WORDS (2 * 2 * 128 * APAD)
#define B_WORDS (2 * 2 * 8 * BPAD)
#define GEMM_SMEM ((A_WORDS + B_WORDS) * 4)

#define AS(b, h, r, k) sA[((((b) * 2 + (h)) * 128 + (r)) * APAD) + (k)]
#define BS(b, h, k, n) sB[((((b) * 2 + (h)) * 8 + (k)) * BPAD) + (n)]

__global__ __launch_bounds__(256, 2) void k_gemm6(const float* __restrict__ A,
                                                  const uint32_t* __restrict__ BH,
                                                  const uint32_t* __restrict__ BL,
                                                  float* __restrict__ C, int M) {
    extern __shared__ uint32_t smem_dyn[];
    uint32_t* sA = smem_dyn;
    uint32_t* sB = smem_dyn + A_WORDS;

    int tid = threadIdx.x, wid = tid >> 5, lane = tid & 31;
    int g = lane >> 2, t = lane & 3;
    int wm = wid & 1, wn = wid >> 1;
    int bm = blockIdx.x * 128;
    int bn = blockIdx.y * 128;

    int a_row  = tid >> 1;
    int a_half = tid & 1;
    int b_kp   = tid >> 5;
    int b_col  = (tid & 31) * 4;

    long long a_base = (long long)(bm + a_row) * DD + a_half * 8;
    bool a_ok = (bm + a_row) < M;
    const float4 z4 = make_float4(0.f, 0.f, 0.f, 0.f);

    float acc[4][4][4];
#pragma unroll
    for (int i = 0; i < 4; i++)
#pragma unroll
        for (int j = 0; j < 4; j++)
#pragma unroll
            for (int q = 0; q < 4; q++) acc[i][j][q] = 0.f;

    {
        float4 v0 = a_ok ? *(const float4*)(A + a_base)     : z4;
        float4 v1 = a_ok ? *(const float4*)(A + a_base + 4) : z4;
        uint4 h, l;
        split2_bf16(v0.x, v0.y, h.x, l.x);
        split2_bf16(v0.z, v0.w, h.y, l.y);
        split2_bf16(v1.x, v1.y, h.z, l.z);
        split2_bf16(v1.z, v1.w, h.w, l.w);
        *(uint4*)&AS(0, 0, a_row, a_half * 4) = h;
        *(uint4*)&AS(0, 1, a_row, a_half * 4) = l;
        uint4 bh4 = *(const uint4*)(BH + (long long)b_kp * DD + bn + b_col);
        uint4 bl4 = *(const uint4*)(BL + (long long)b_kp * DD + bn + b_col);
        *(uint4*)&BS(0, 0, b_kp, b_col) = bh4;
        *(uint4*)&BS(0, 1, b_kp, b_col) = bl4;
    }
    __syncthreads();

    const int NSTEP = DD / 16;
    for (int k0 = 0; k0 < NSTEP; k0++) {
        int cur = k0 & 1, nxt = cur ^ 1;
        bool more = (k0 + 1) < NSTEP;

        float4 v0 = z4, v1 = z4;
        uint4 pbh = {0, 0, 0, 0}, pbl = {0, 0, 0, 0};
        if (more) {
            int kb = (k0 + 1) * 16;
            v0 = a_ok ? *(const float4*)(A + a_base + kb)     : z4;
            v1 = a_ok ? *(const float4*)(A + a_base + kb + 4) : z4;
            int kp = (k0 + 1) * 8 + b_kp;
            pbh = *(const uint4*)(BH + (long long)kp * DD + bn + b_col);
            pbl = *(const uint4*)(BL + (long long)kp * DD + bn + b_col);
        }

        uint32_t bh[4][2], bl[4][2];
#pragma unroll
        for (int j = 0; j < 4; j++) {
            int n = wn * 32 + 8 * j + g;
            bh[j][0] = BS(cur, 0, t, n);     bh[j][1] = BS(cur, 0, t + 4, n);
            bl[j][0] = BS(cur, 1, t, n);     bl[j][1] = BS(cur, 1, t + 4, n);
        }
#pragma unroll
        for (int i = 0; i < 4; i++) {
            int r = wm * 64 + i * 16;
            uint32_t ah[4], al[4];
            ah[0] = AS(cur, 0, r + g, t);      ah[1] = AS(cur, 0, r + g + 8, t);
            ah[2] = AS(cur, 0, r + g, t + 4);  ah[3] = AS(cur, 0, r + g + 8, t + 4);
            al[0] = AS(cur, 1, r + g, t);      al[1] = AS(cur, 1, r + g + 8, t);
            al[2] = AS(cur, 1, r + g, t + 4);  al[3] = AS(cur, 1, r + g + 8, t + 4);
#pragma unroll
            for (int j = 0; j < 4; j++) {
                mma16(acc[i][j], ah, bh[j]);
                mma16(acc[i][j], ah, bl[j]);
                mma16(acc[i][j], al, bh[j]);
            }
        }

        if (more) {
            uint4 h, l;
            split2_bf16(v0.x, v0.y, h.x, l.x);
            split2_bf16(v0.z, v0.w, h.y, l.y);
            split2_bf16(v1.x, v1.y, h.z, l.z);
            split2_bf16(v1.z, v1.w, h.w, l.w);
            *(uint4*)&AS(nxt, 0, a_row, a_half * 4) = h;
            *(uint4*)&AS(nxt, 1, a_row, a_half * 4) = l;
            *(uint4*)&BS(nxt, 0, b_kp, b_col) = pbh;
            *(uint4*)&BS(nxt, 1, b_kp, b_col) = pbl;
        }
        __syncthreads();
    }

#pragma unroll
    for (int i = 0; i < 4; i++)
#pragma unroll
        for (int j = 0; j < 4; j++) {
            int row0 = bm + wm * 64 + i * 16 + g;
            int col  = bn + wn * 32 + 8 * j + 2 * t;
            if (row0 < M) {
                float2 v = {acc[i][j][0], acc[i][j][1]};
                *(float2*)(C + (long long)row0 * DD + col) = v;
            }
            int row1 = row0 + 8;
            if (row1 < M) {
                float2 v = {acc[i][j][2], acc[i][j][3]};
                *(float2*)(C + (long long)row1 * DD + col) = v;
            }
        }
}

// -------- fused aggregate (R12 form): 1 warp/node, unroll x4, packed CSR -------
__global__ __launch_bounds__(256) void k_aggregate(const float* __restrict__ tmp,
                                                   float* __restrict__ out,
                                                   const float* __restrict__ bias) {
    int node = (int)(((long long)blockIdx.x * blockDim.x + threadIdx.x) >> 5);
    int lane = threadIdx.x & 31;
    if (node >= NN) return;

    float di = g_dinv[node];
    float ws = di * di;
    const float4* r = (const float4*)(tmp + (long long)node * DD);
    float4 v0 = r[lane], v1 = r[lane + 32];
    float4 a0 = {v0.x * ws, v0.y * ws, v0.z * ws, v0.w * ws};
    float4 a1 = {v1.x * ws, v1.y * ws, v1.z * ws, v1.w * ws};

    int p = g_rowptr[node], pe = g_rowptr[node + 1];
    for (; p + 4 <= pe; p += 4) {
        uint2 e0 = g_csr[p],     e1 = g_csr[p + 1];
        uint2 e2 = g_csr[p + 2], e3 = g_csr[p + 3];
        const float4* r0 = (const float4*)(tmp + (long long)e0.x * DD);
        const float4* r1 = (const float4*)(tmp + (long long)e1.x * DD);
        const float4* r2 = (const float4*)(tmp + (long long)e2.x * DD);
        const float4* r3 = (const float4*)(tmp + (long long)e3.x * DD);
        float4 u00 = r0[lane], u01 = r0[lane + 32];
        float4 u10 = r1[lane], u11 = r1[lane + 32];
        float4 u20 = r2[lane], u21 = r2[lane + 32];
        float4 u30 = r3[lane], u31 = r3[lane + 32];
        float w0 = __uint_as_float(e0.y), w1 = __uint_as_float(e1.y);
        float w2 = __uint_as_float(e2.y), w3 = __uint_as_float(e3.y);
        a0.x += w0 * u00.x + w1 * u10.x + w2 * u20.x + w3 * u30.x;
        a0.y += w0 * u00.y + w1 * u10.y + w2 * u20.y + w3 * u30.y;
        a0.z += w0 * u00.z + w1 * u10.z + w2 * u20.z + w3 * u30.z;
        a0.w += w0 * u00.w + w1 * u10.w + w2 * u20.w + w3 * u30.w;
        a1.x += w0 * u01.x + w1 * u11.x + w2 * u21.x + w3 * u31.x;
        a1.y += w0 * u01.y + w1 * u11.y + w2 * u21.y + w3 * u31.y;
        a1.z += w0 * u01.z + w1 * u11.z + w2 * u21.z + w3 * u31.z;
        a1.w += w0 * u01.w + w1 * u11.w + w2 * u21.w + w3 * u31.w;
    }
    for (; p < pe; ++p) {
        uint2 e = g_csr[p];
        float w = __uint_as_float(e.y);
        const float4* rs = (const float4*)(tmp + (long long)e.x * DD);
        float4 u0 = rs[lane], u1 = rs[lane + 32];
        a0.x += w * u0.x; a0.y += w * u0.y; a0.z += w * u0.z; a0.w += w * u0.w;
        a1.x += w * u1.x; a1.y += w * u1.y; a1.z += w * u1.z; a1.w += w * u1.w;
    }

    float4 b0 = ((const float4*)bias)[lane];
    float4 b1 = ((const float4*)bias)[lane + 32];
    a0.x = fmaxf(a0.x + b0.x, 0.f); a0.y = fmaxf(a0.y + b0.y, 0.f);
    a0.z = fmaxf(a0.z + b0.z, 0.f); a0.w = fmaxf(a0.w + b0.w, 0.f);
    a1.x = fmaxf(a1.x + b1.x, 0.f); a1.y = fmaxf(a1.y + b1.y, 0.f);
    a1.z = fmaxf(a1.z + b1.z, 0.f); a1.w = fmaxf(a1.w + b1.w, 0.f);

    float4* o = (float4*)(out + (long long)node * DD);
    o[lane] = a0;
    o[lane + 32] = a1;
}

// ---------------- pool (batch sorted) + fc ----------------
__global__ void k_pool2(const float* __restrict__ h, const void* __restrict__ batch) {
    int col = threadIdx.x;
    int n0 = blockIdx.x * 128;
    int n1 = min(n0 + 128, NN);
    int is32 = g_flags[1];
    int cur = (int)fetch_idx(batch, n0, is32);
    float acc = 0.f;
    int cnt = 0;
    for (int n = n0; n < n1; n++) {
        int gid = (int)fetch_idx(batch, n, is32);
        if (gid != cur) {
            atomicAdd(&g_pool[cur * DD + col], acc);
            if (col == 0) atomicAdd(&g_cnt[cur], (float)cnt);
            acc = 0.f; cnt = 0; cur = gid;
        }
        acc += h[(long long)n * DD + col];
        cnt++;
    }
    atomicAdd(&g_pool[cur * DD + col], acc);
    if (col == 0) atomicAdd(&g_cnt[cur], (float)cnt);
}

// fc + epoch reset of g_flags for the next graph replay
__global__ void k_fc(const float* __restrict__ Wfc, const float* __restrict__ bfc,
                     float* __restrict__ out) {
    int tt = blockIdx.x * blockDim.x + threadIdx.x;
    if (tt < 2 && blockIdx.x == 0) g_flags[tt] = 0;
    if (tt >= GG * DOUT) return;
    int g = tt >> 4, o = tt & 15;
    float inv = 1.0f / fmaxf(g_cnt[g], 1.0f);
    float acc = 0.f;
#pragma unroll 8
    for (int k = 0; k < DD; k++) acc += g_pool[g * DD + k] * Wfc[k * DOUT + o];
    out[tt] = acc * inv + bfc[o];
}

// ---------------- launch ----------------
extern "C" void kernel_launch(void* const* d_in, const int* in_sizes, int n_in,
                              void* d_out, int out_size) {
    const float* x     = (const float*)d_in[0];
    const void*  ei    = d_in[1];
    const void*  batch = d_in[2];
    const float* W1 = (const float*)d_in[3];  const float* b1 = (const float*)d_in[4];
    const float* W2 = (const float*)d_in[5];  const float* b2 = (const float*)d_in[6];
    const float* W3 = (const float*)d_in[7];  const float* b3 = (const float*)d_in[8];
    const float* Wfc = (const float*)d_in[9]; const float* bfc = (const float*)d_in[10];
    float* out = (float*)d_out;

    long long E = in_sizes[1] / 2;
    long long ei_words = (long long)in_sizes[1];
    long long bt_words = (long long)in_sizes[2];

    float *S0, *S1;
    uint32_t *WpH, *WpL;
    cudaGetSymbolAddress((void**)&S0, g_S0);
    cudaGetSymbolAddress((void**)&S1, g_S1);
    cudaGetSymbolAddress((void**)&WpH, g_WpH);
    cudaGetSymbolAddress((void**)&WpL, g_WpL);

    cudaFuncSetAttribute(k_gemm6, cudaFuncAttributeMaxDynamicSharedMemorySize,
                         GEMM_SMEM);

    dim3 gemm_grid((NN + 127) / 128, 2);
    int det_blocks = (int)((ei_words / 2 + 255) / 256);
    int init_blocks = INIT_PREPW_BLKS + INIT_ZERO_BLKS + det_blocks;
    const float* bs[3] = {b1, b2, b3};

    k_init<<<init_blocks, 256>>>(W1, W2, W3, (const unsigned*)ei, ei_words,
                                 (const unsigned*)batch, bt_words);            // 1
    k_count<<<(int)((E + 255) / 256), 256>>>(ei, E);                           // 2
    k_scan_dinv<<<1, 1024>>>();                                                // 3
    k_gemm6<<<gemm_grid, 256, GEMM_SMEM>>>(x, WpH, WpL, S0, NN);               // 4 (profiled)
    k_fill<<<(int)((E + 255) / 256), 256>>>(ei, E);                            // 5
    k_aggregate<<<(NN * 32 + 255) / 256, 256>>>(S0, S1, bs[0]);                // 6

    const float* in = S1;
    for (int l = 1; l < 3; l++) {
        k_gemm6<<<gemm_grid, 256, GEMM_SMEM>>>(in, WpH + (size_t)l * 128 * DD,
                                               WpL + (size_t)l * 128 * DD, S0, NN);
        k_aggregate<<<(NN * 32 + 255) / 256, 256>>>(S0, S1, bs[l]);
        in = S1;
    }

    k_pool2<<<(NN + 127) / 128, 256>>>(S1, batch);
    k_fc<<<(GG * DOUT + 255) / 256, 256>>>(Wfc, bfc, out);
}

// round 16
// speedup vs baseline: 1.1692x; 1.1229x over previous
#include <cuda_runtime.h>
#include <cuda_fp16.h>
#include <cstdint>

#define NN 50000
#define EE 400000
#define DD 256
#define GG 64
#define DOUT 16

// ---------------- static scratch ----------------
__device__ float    g_S0[NN * DD];        // fp16 words live in first half when packed
__device__ float    g_S1[NN * DD];
__device__ uint32_t g_WpH[3][128 * DD];   // W packed bf16-hi pairs: [k/2][n]
__device__ uint32_t g_WpL[3][128 * DD];   // W packed bf16-lo pairs
__device__ int      g_degi[NN];
__device__ float    g_dinv[NN];
__device__ int      g_rowptr[NN + 1];
__device__ int      g_cursor[NN];
__device__ uint2    g_csr[EE];            // {src, weight-bits}
__device__ float    g_pool[GG * DD];
__device__ float    g_cnt[GG];
__device__ int      g_flags[2];           // zero-init at load; reset by k_fc

// ---------------- helpers ----------------
__device__ __forceinline__ void split2_bf16(float x0, float x1,
                                            uint32_t& whi, uint32_t& wlo) {
    uint32_t b0 = __float_as_uint(x0), b1 = __float_as_uint(x1);
    whi = __byte_perm(b0, b1, 0x7632);
    float h0 = __uint_as_float(b0 & 0xFFFF0000u);
    float h1 = __uint_as_float(b1 & 0xFFFF0000u);
    float l0 = x0 - h0, l1 = x1 - h1;
    asm("cvt.rn.bf16x2.f32 %0, %1, %2;" : "=r"(wlo) : "f"(l1), "f"(l0));
}

__device__ __forceinline__ float2 h2f(uint32_t w) {
    __half2 h = *reinterpret_cast<__half2*>(&w);
    return __half22float2(h);
}
__device__ __forceinline__ uint32_t f2h(float a, float b) {
    __half2 h = __floats2half2_rn(a, b);
    return *reinterpret_cast<uint32_t*>(&h);
}

__device__ __forceinline__ void mma16(float* c, const uint32_t* a, const uint32_t* b) {
    asm volatile(
        "mma.sync.aligned.m16n8k16.row.col.f32.bf16.bf16.f32 "
        "{%0,%1,%2,%3}, {%4,%5,%6,%7}, {%8,%9}, {%0,%1,%2,%3};"
        : "+f"(c[0]), "+f"(c[1]), "+f"(c[2]), "+f"(c[3])
        : "r"(a[0]), "r"(a[1]), "r"(a[2]), "r"(a[3]), "r"(b[0]), "r"(b[1]));
}

__device__ __forceinline__ long long fetch_idx(const void* p, long long i, int is32) {
    if (is32) return (long long)((const int*)p)[i];
    return ((const long long*)p)[i];
}

// ---------------- launch 1: fused prepw + zero + x->fp16 + detect --------------
#define INIT_PREPW_BLKS 128
#define INIT_ZERO_BLKS  260
#define INIT_XCVT_BLKS  ((NN * 32 + 255) / 256)   // 6250
__global__ void k_init(const float* __restrict__ W1, const float* __restrict__ W2,
                       const float* __restrict__ W3,
                       const float* __restrict__ x, uint32_t* __restrict__ xh,
                       const unsigned* __restrict__ ei, long long ei_words,
                       const unsigned* __restrict__ bt, long long bt_words) {
    int b = blockIdx.x;
    if (b < INIT_PREPW_BLKS) {
        int idx = b * 256 + threadIdx.x;          // k'(128) x n(256)
        int kp = idx >> 8, n = idx & 255;
        const float* Ws[3] = {W1, W2, W3};
#pragma unroll
        for (int l = 0; l < 3; l++) {
            float x0 = Ws[l][(2 * kp) * DD + n];
            float x1 = Ws[l][(2 * kp + 1) * DD + n];
            uint32_t h, lo;
            split2_bf16(x0, x1, h, lo);
            g_WpH[l][kp * DD + n] = h;
            g_WpL[l][kp * DD + n] = lo;
        }
        return;
    }
    if (b < INIT_PREPW_BLKS + INIT_ZERO_BLKS) {
        int i = (b - INIT_PREPW_BLKS) * 256 + threadIdx.x;
        if (i < NN) g_degi[i] = 0;
        int j = i - NN;
        if (j >= 0 && j < GG * DD) g_pool[j] = 0.f;
        int k = j - GG * DD;
        if (k >= 0 && k < GG) g_cnt[k] = 0.f;
        return;
    }
    if (b < INIT_PREPW_BLKS + INIT_ZERO_BLKS + INIT_XCVT_BLKS) {
        int i = (b - INIT_PREPW_BLKS - INIT_ZERO_BLKS) * 256 + threadIdx.x;
        if (i < NN * 32) {
            int n = i >> 5, q = i & 31;            // q covers cols [q*8, q*8+8)
            const float* src = x + (long long)n * DD + q * 8;
            float4 v0 = *(const float4*)(src);
            float4 v1 = *(const float4*)(src + 4);
            uint4 o;
            o.x = f2h(v0.x, v0.y); o.y = f2h(v0.z, v0.w);
            o.z = f2h(v1.x, v1.y); o.w = f2h(v1.z, v1.w);
            *(uint4*)&xh[n * 128 + q * 4] = o;
        }
        return;
    }
    long long base = (long long)(b - INIT_PREPW_BLKS - INIT_ZERO_BLKS - INIT_XCVT_BLKS)
                     * 256 + threadIdx.x;
    long long i = 2 * base + 1;
    unsigned v0 = (i < ei_words) ? ei[i] : 0u;
    unsigned v1 = (i < bt_words) ? bt[i] : 0u;
#pragma unroll
    for (int o = 16; o > 0; o >>= 1) {
        v0 |= __shfl_xor_sync(0xffffffffu, v0, o);
        v1 |= __shfl_xor_sync(0xffffffffu, v1, o);
    }
    if ((threadIdx.x & 31) == 0) {
        if (v0) atomicOr(&g_flags[0], 1);
        if (v1) atomicOr(&g_flags[1], 1);
    }
}

__global__ void k_count(const void* __restrict__ ei, long long E) {
    long long e = (long long)blockIdx.x * blockDim.x + threadIdx.x;
    if (e >= E) return;
    int is32 = g_flags[0];
    long long d = fetch_idx(ei, E + e, is32);
    atomicAdd(&g_degi[d], 1);
}

__global__ void k_scan_dinv() {
    __shared__ int part[1024];
    const int CH = (NN + 1023) / 1024;
    int t = threadIdx.x;
    int beg = t * CH, end = min(beg + CH, NN);
    int s = 0;
    for (int i = beg; i < end; i++) {
        int d = g_degi[i];
        g_dinv[i] = rsqrtf((float)d + 1.0f);
        s += d;
    }
    part[t] = s;
    __syncthreads();
    for (int off = 1; off < 1024; off <<= 1) {
        int v = (t >= off) ? part[t - off] : 0;
        __syncthreads();
        part[t] += v;
        __syncthreads();
    }
    int excl = (t == 0) ? 0 : part[t - 1];
    for (int i = beg; i < end; i++) {
        g_rowptr[i] = excl;
        g_cursor[i] = excl;
        excl += g_degi[i];
    }
    if (t == 1023) g_rowptr[NN] = part[1023];
}

__global__ void k_fill(const void* __restrict__ ei, long long E) {
    long long e = (long long)blockIdx.x * blockDim.x + threadIdx.x;
    if (e >= E) return;
    int is32 = g_flags[0];
    int s = (int)fetch_idx(ei, e, is32);
    int d = (int)fetch_idx(ei, E + e, is32);
    int pos = atomicAdd(&g_cursor[d], 1);
    float w = g_dinv[s] * g_dinv[d];
    g_csr[pos] = make_uint2((uint32_t)s, __float_as_uint(w));
}

// ---------------- bf16x2-split GEMM, fp16 A + fp16 C ---------------------------
// C16[M,256(half)] = A16[M,256(half)] @ W. Same tiling as R9/R12:
// block 128x128 (grid 391 x 2), 8 warps (2m x 4n), warp tile 64x32, BK=16.
#define APAD 12
#define BPAD 136
#define A_WORDS (2 * 2 * 128 * APAD)
#define B_WORDS (2 * 2 * 8 * BPAD)
#define GEMM_SMEM ((A_WORDS + B_WORDS) * 4)

#define AS(b, h, r, k) sA[((((b) * 2 + (h)) * 128 + (r)) * APAD) + (k)]
#define BS(b, h, k, n) sB[((((b) * 2 + (h)) * 8 + (k)) * BPAD) + (n)]

__global__ __launch_bounds__(256, 2) void k_gemm8(const uint32_t* __restrict__ A16,
                                                  const uint32_t* __restrict__ BH,
                                                  const uint32_t* __restrict__ BL,
                                                  uint32_t* __restrict__ C16, int M) {
    extern __shared__ uint32_t smem_dyn[];
    uint32_t* sA = smem_dyn;
    uint32_t* sB = smem_dyn + A_WORDS;

    int tid = threadIdx.x, wid = tid >> 5, lane = tid & 31;
    int g = lane >> 2, t = lane & 3;
    int wm = wid & 1, wn = wid >> 1;
    int bm = blockIdx.x * 128;
    int bn = blockIdx.y * 128;

    int a_row  = tid >> 1;                 // 0..127
    int a_half = tid & 1;                  // k-halves [a_half*8, +8) of the 16-chunk
    int b_kp   = tid >> 5;
    int b_col  = (tid & 31) * 4;

    int arow_c = bm + a_row < M ? bm + a_row : 0;
    bool a_ok = (bm + a_row) < M;
    const uint32_t* Aw = A16 + (long long)arow_c * 128 + a_half * 4;
    const uint4 zu4 = make_uint4(0, 0, 0, 0);

    float acc[4][4][4];
#pragma unroll
    for (int i = 0; i < 4; i++)
#pragma unroll
        for (int j = 0; j < 4; j++)
#pragma unroll
            for (int q = 0; q < 4; q++) acc[i][j][q] = 0.f;

    // prologue: stage chunk 0 into buffer 0
    {
        uint4 va = a_ok ? *(const uint4*)(Aw) : zu4;
        uint4 h, l;
        float2 f;
        f = h2f(va.x); split2_bf16(f.x, f.y, h.x, l.x);
        f = h2f(va.y); split2_bf16(f.x, f.y, h.y, l.y);
        f = h2f(va.z); split2_bf16(f.x, f.y, h.z, l.z);
        f = h2f(va.w); split2_bf16(f.x, f.y, h.w, l.w);
        *(uint4*)&AS(0, 0, a_row, a_half * 4) = h;
        *(uint4*)&AS(0, 1, a_row, a_half * 4) = l;
        uint4 bh4 = *(const uint4*)(BH + (long long)b_kp * DD + bn + b_col);
        uint4 bl4 = *(const uint4*)(BL + (long long)b_kp * DD + bn + b_col);
        *(uint4*)&BS(0, 0, b_kp, b_col) = bh4;
        *(uint4*)&BS(0, 1, b_kp, b_col) = bl4;
    }
    __syncthreads();

    const int NSTEP = DD / 16;
    for (int k0 = 0; k0 < NSTEP; k0++) {
        int cur = k0 & 1, nxt = cur ^ 1;
        bool more = (k0 + 1) < NSTEP;

        uint4 va = zu4, pbh = zu4, pbl = zu4;
        if (more) {
            va = a_ok ? *(const uint4*)(Aw + (k0 + 1) * 8) : zu4;
            int kp = (k0 + 1) * 8 + b_kp;
            pbh = *(const uint4*)(BH + (long long)kp * DD + bn + b_col);
            pbl = *(const uint4*)(BL + (long long)kp * DD + bn + b_col);
        }

        uint32_t bh[4][2], bl[4][2];
#pragma unroll
        for (int j = 0; j < 4; j++) {
            int n = wn * 32 + 8 * j + g;
            bh[j][0] = BS(cur, 0, t, n);     bh[j][1] = BS(cur, 0, t + 4, n);
            bl[j][0] = BS(cur, 1, t, n);     bl[j][1] = BS(cur, 1, t + 4, n);
        }
#pragma unroll
        for (int i = 0; i < 4; i++) {
            int r = wm * 64 + i * 16;
            uint32_t ah[4], al[4];
            ah[0] = AS(cur, 0, r + g, t);      ah[1] = AS(cur, 0, r + g + 8, t);
            ah[2] = AS(cur, 0, r + g, t + 4);  ah[3] = AS(cur, 0, r + g + 8, t + 4);
            al[0] = AS(cur, 1, r + g, t);      al[1] = AS(cur, 1, r + g + 8, t);
            al[2] = AS(cur, 1, r + g, t + 4);  al[3] = AS(cur, 1, r + g + 8, t + 4);
#pragma unroll
            for (int j = 0; j < 4; j++) {
                mma16(acc[i][j], ah, bh[j]);
                mma16(acc[i][j], ah, bl[j]);
                mma16(acc[i][j], al, bh[j]);
            }
        }

        if (more) {
            uint4 h, l;
            float2 f;
            f = h2f(va.x); split2_bf16(f.x, f.y, h.x, l.x);
            f = h2f(va.y); split2_bf16(f.x, f.y, h.y, l.y);
            f = h2f(va.z); split2_bf16(f.x, f.y, h.z, l.z);
            f = h2f(va.w); split2_bf16(f.x, f.y, h.w, l.w);
            *(uint4*)&AS(nxt, 0, a_row, a_half * 4) = h;
            *(uint4*)&AS(nxt, 1, a_row, a_half * 4) = l;
            *(uint4*)&BS(nxt, 0, b_kp, b_col) = pbh;
            *(uint4*)&BS(nxt, 1, b_kp, b_col) = pbl;
        }
        __syncthreads();
    }

    // epilogue: pack (col, col+1) fp32 pairs -> half2 word
#pragma unroll
    for (int i = 0; i < 4; i++)
#pragma unroll
        for (int j = 0; j < 4; j++) {
            int row0 = bm + wm * 64 + i * 16 + g;
            int widx = (bn >> 1) + wn * 16 + 4 * j + t;
            if (row0 < M)
                C16[(long long)row0 * 128 + widx] = f2h(acc[i][j][0], acc[i][j][1]);
            int row1 = row0 + 8;
            if (row1 < M)
                C16[(long long)row1 * 128 + widx] = f2h(acc[i][j][2], acc[i][j][3]);
        }
}

// -------- fused aggregate on fp16 rows: 1 warp/node, unroll x4 -----------------
// tmp rows: 128 uint32 (256 halves). Lane covers words [lane*4, +4) = cols [lane*8,+8).
__global__ __launch_bounds__(256) void k_aggregate_h(const uint32_t* __restrict__ tmp,
                                                     uint32_t* __restrict__ outh,
                                                     float* __restrict__ outf,
                                                     const float* __restrict__ bias,
                                                     int pack) {
    int node = (int)(((long long)blockIdx.x * blockDim.x + threadIdx.x) >> 5);
    int lane = threadIdx.x & 31;
    if (node >= NN) return;

    float a[8];
    {
        float di = g_dinv[node];
        float ws = di * di;
        uint4 v = *(const uint4*)(tmp + (long long)node * 128 + lane * 4);
        float2 f0 = h2f(v.x), f1 = h2f(v.y), f2 = h2f(v.z), f3 = h2f(v.w);
        a[0] = ws * f0.x; a[1] = ws * f0.y; a[2] = ws * f1.x; a[3] = ws * f1.y;
        a[4] = ws * f2.x; a[5] = ws * f2.y; a[6] = ws * f3.x; a[7] = ws * f3.y;
    }

    int p = g_rowptr[node], pe = g_rowptr[node + 1];
    for (; p + 4 <= pe; p += 4) {
        uint2 e0 = g_csr[p],     e1 = g_csr[p + 1];
        uint2 e2 = g_csr[p + 2], e3 = g_csr[p + 3];
        uint4 v0 = *(const uint4*)(tmp + (long long)e0.x * 128 + lane * 4);
        uint4 v1 = *(const uint4*)(tmp + (long long)e1.x * 128 + lane * 4);
        uint4 v2 = *(const uint4*)(tmp + (long long)e2.x * 128 + lane * 4);
        uint4 v3 = *(const uint4*)(tmp + (long long)e3.x * 128 + lane * 4);
        float w0 = __uint_as_float(e0.y), w1 = __uint_as_float(e1.y);
        float w2 = __uint_as_float(e2.y), w3 = __uint_as_float(e3.y);
        float2 f;
        f = h2f(v0.x); a[0] += w0 * f.x; a[1] += w0 * f.y;
        f = h2f(v0.y); a[2] += w0 * f.x; a[3] += w0 * f.y;
        f = h2f(v0.z); a[4] += w0 * f.x; a[5] += w0 * f.y;
        f = h2f(v0.w); a[6] += w0 * f.x; a[7] += w0 * f.y;
        f = h2f(v1.x); a[0] += w1 * f.x; a[1] += w1 * f.y;
        f = h2f(v1.y); a[2] += w1 * f.x; a[3] += w1 * f.y;
        f = h2f(v1.z); a[4] += w1 * f.x; a[5] += w1 * f.y;
        f = h2f(v1.w); a[6] += w1 * f.x; a[7] += w1 * f.y;
        f = h2f(v2.x); a[0] += w2 * f.x; a[1] += w2 * f.y;
        f = h2f(v2.y); a[2] += w2 * f.x; a[3] += w2 * f.y;
        f = h2f(v2.z); a[4] += w2 * f.x; a[5] += w2 * f.y;
        f = h2f(v2.w); a[6] += w2 * f.x; a[7] += w2 * f.y;
        f = h2f(v3.x); a[0] += w3 * f.x; a[1] += w3 * f.y;
        f = h2f(v3.y); a[2] += w3 * f.x; a[3] += w3 * f.y;
        f = h2f(v3.z); a[4] += w3 * f.x; a[5] += w3 * f.y;
        f = h2f(v3.w); a[6] += w3 * f.x; a[7] += w3 * f.y;
    }
    for (; p < pe; ++p) {
        uint2 e = g_csr[p];
        float w = __uint_as_float(e.y);
        uint4 v = *(const uint4*)(tmp + (long long)e.x * 128 + lane * 4);
        float2 f;
        f = h2f(v.x); a[0] += w * f.x; a[1] += w * f.y;
        f = h2f(v.y); a[2] += w * f.x; a[3] += w * f.y;
        f = h2f(v.z); a[4] += w * f.x; a[5] += w * f.y;
        f = h2f(v.w); a[6] += w * f.x; a[7] += w * f.y;
    }

    float4 b0 = *(const float4*)(bias + lane * 8);
    float4 b1 = *(const float4*)(bias + lane * 8 + 4);
    a[0] = fmaxf(a[0] + b0.x, 0.f); a[1] = fmaxf(a[1] + b0.y, 0.f);
    a[2] = fmaxf(a[2] + b0.z, 0.f); a[3] = fmaxf(a[3] + b0.w, 0.f);
    a[4] = fmaxf(a[4] + b1.x, 0.f); a[5] = fmaxf(a[5] + b1.y, 0.f);
    a[6] = fmaxf(a[6] + b1.z, 0.f); a[7] = fmaxf(a[7] + b1.w, 0.f);

    if (pack) {
        uint4 o;
        o.x = f2h(a[0], a[1]); o.y = f2h(a[2], a[3]);
        o.z = f2h(a[4], a[5]); o.w = f2h(a[6], a[7]);
        *(uint4*)&outh[(long long)node * 128 + lane * 4] = o;
    } else {
        float4 o0 = {a[0], a[1], a[2], a[3]};
        float4 o1 = {a[4], a[5], a[6], a[7]};
        *(float4*)(outf + (long long)node * DD + lane * 8) = o0;
        *(float4*)(outf + (long long)node * DD + lane * 8 + 4) = o1;
    }
}

// ---------------- pool (batch sorted) + fc ----------------
__global__ void k_pool2(const float* __restrict__ h, const void* __restrict__ batch) {
    int col = threadIdx.x;
    int n0 = blockIdx.x * 128;
    int n1 = min(n0 + 128, NN);
    int is32 = g_flags[1];
    int cur = (int)fetch_idx(batch, n0, is32);
    float acc = 0.f;
    int cnt = 0;
    for (int n = n0; n < n1; n++) {
        int gid = (int)fetch_idx(batch, n, is32);
        if (gid != cur) {
            atomicAdd(&g_pool[cur * DD + col], acc);
            if (col == 0) atomicAdd(&g_cnt[cur], (float)cnt);
            acc = 0.f; cnt = 0; cur = gid;
        }
        acc += h[(long long)n * DD + col];
        cnt++;
    }
    atomicAdd(&g_pool[cur * DD + col], acc);
    if (col == 0) atomicAdd(&g_cnt[cur], (float)cnt);
}

__global__ void k_fc(const float* __restrict__ Wfc, const float* __restrict__ bfc,
                     float* __restrict__ out) {
    int tt = blockIdx.x * blockDim.x + threadIdx.x;
    if (tt < 2 && blockIdx.x == 0) g_flags[tt] = 0;
    if (tt >= GG * DOUT) return;
    int g = tt >> 4, o = tt & 15;
    float inv = 1.0f / fmaxf(g_cnt[g], 1.0f);
    float acc = 0.f;
#pragma unroll 8
    for (int k = 0; k < DD; k++) acc += g_pool[g * DD + k] * Wfc[k * DOUT + o];
    out[tt] = acc * inv + bfc[o];
}

// ---------------- launch ----------------
extern "C" void kernel_launch(void* const* d_in, const int* in_sizes, int n_in,
                              void* d_out, int out_size) {
    const float* x     = (const float*)d_in[0];
    const void*  ei    = d_in[1];
    const void*  batch = d_in[2];
    const float* W1 = (const float*)d_in[3];  const float* b1 = (const float*)d_in[4];
    const float* W2 = (const float*)d_in[5];  const float* b2 = (const float*)d_in[6];
    const float* W3 = (const float*)d_in[7];  const float* b3 = (const float*)d_in[8];
    const float* Wfc = (const float*)d_in[9]; const float* bfc = (const float*)d_in[10];
    float* out = (float*)d_out;

    long long E = in_sizes[1] / 2;
    long long ei_words = (long long)in_sizes[1];
    long long bt_words = (long long)in_sizes[2];

    float *S0, *S1;
    uint32_t *WpH, *WpL;
    cudaGetSymbolAddress((void**)&S0, g_S0);
    cudaGetSymbolAddress((void**)&S1, g_S1);
    cudaGetSymbolAddress((void**)&WpH, g_WpH);
    cudaGetSymbolAddress((void**)&WpL, g_WpL);
    uint32_t* S0w = (uint32_t*)S0;
    uint32_t* S1w = (uint32_t*)S1;

    cudaFuncSetAttribute(k_gemm8, cudaFuncAttributeMaxDynamicSharedMemorySize,
                         GEMM_SMEM);

    dim3 gemm_grid((NN + 127) / 128, 2);
    int det_blocks = (int)((ei_words / 2 + 255) / 256);
    int init_blocks = INIT_PREPW_BLKS + INIT_ZERO_BLKS + INIT_XCVT_BLKS + det_blocks;
    const float* bs[3] = {b1, b2, b3};

    k_init<<<init_blocks, 256>>>(W1, W2, W3, x, S1w, (const unsigned*)ei, ei_words,
                                 (const unsigned*)batch, bt_words);            // 1
    k_count<<<(int)((E + 255) / 256), 256>>>(ei, E);                           // 2
    k_scan_dinv<<<1, 1024>>>();                                                // 3
    k_gemm8<<<gemm_grid, 256, GEMM_SMEM>>>(S1w, WpH, WpL, S0w, NN);            // 4 (profiled)
    k_fill<<<(int)((E + 255) / 256), 256>>>(ei, E);                            // 5
    k_aggregate_h<<<(NN * 32 + 255) / 256, 256>>>(S0w, S1w, S1, bs[0], 1);     // 6

    for (int l = 1; l < 3; l++) {
        k_gemm8<<<gemm_grid, 256, GEMM_SMEM>>>(S1w, WpH + (size_t)l * 128 * DD,
                                               WpL + (size_t)l * 128 * DD, S0w, NN);
        k_aggregate_h<<<(NN * 32 + 255) / 256, 256>>>(S0w, S1w, S1, bs[l],
                                                      l == 2 ? 0 : 1);
    }

    k_pool2<<<(NN + 127) / 128, 256>>>(S1, batch);
    k_fc<<<(GG * DOUT + 255) / 256, 256>>>(Wfc, bfc, out);
}

// round 17
// speedup vs baseline: 1.3238x; 1.1322x over previous
#include <cuda_runtime.h>
#include <cuda_fp16.h>
#include <cstdint>

#define NN 50000
#define EE 400000
#define DD 256
#define GG 64
#define DOUT 16

// ---------------- static scratch ----------------
__device__ float    g_S0[NN * DD];        // fp16 words live in first half when packed
__device__ float    g_S1[NN * DD];
__device__ uint32_t g_WpH[3][128 * DD];   // W packed fp16-hi pairs: [k/2][n]
__device__ uint32_t g_WpL[3][128 * DD];   // W packed fp16-lo pairs (residual)
__device__ int      g_degi[NN];
__device__ float    g_dinv[NN];
__device__ int      g_rowptr[NN + 1];
__device__ int      g_cursor[NN];
__device__ uint2    g_csr[EE];            // {src, weight-bits}
__device__ float    g_pool[GG * DD];
__device__ float    g_cnt[GG];
__device__ int      g_flags[2];           // zero-init at load; reset by k_fc

// ---------------- helpers ----------------
__device__ __forceinline__ float2 h2f(uint32_t w) {
    __half2 h = *reinterpret_cast<__half2*>(&w);
    return __half22float2(h);
}
__device__ __forceinline__ uint32_t f2h(float a, float b) {
    __half2 h = __floats2half2_rn(a, b);
    return *reinterpret_cast<uint32_t*>(&h);
}

__device__ __forceinline__ void mma16f(float* c, const uint32_t* a, const uint32_t* b) {
    asm volatile(
        "mma.sync.aligned.m16n8k16.row.col.f32.f16.f16.f32 "
        "{%0,%1,%2,%3}, {%4,%5,%6,%7}, {%8,%9}, {%0,%1,%2,%3};"
        : "+f"(c[0]), "+f"(c[1]), "+f"(c[2]), "+f"(c[3])
        : "r"(a[0]), "r"(a[1]), "r"(a[2]), "r"(a[3]), "r"(b[0]), "r"(b[1]));
}

__device__ __forceinline__ long long fetch_idx(const void* p, long long i, int is32) {
    if (is32) return (long long)((const int*)p)[i];
    return ((const long long*)p)[i];
}

// ---------------- launch 1: fused prepw + zero + x->fp16 + detect --------------
#define INIT_PREPW_BLKS 128
#define INIT_ZERO_BLKS  260
#define INIT_XCVT_BLKS  ((NN * 32 + 255) / 256)   // 6250
__global__ void k_init(const float* __restrict__ W1, const float* __restrict__ W2,
                       const float* __restrict__ W3,
                       const float* __restrict__ x, uint32_t* __restrict__ xh,
                       const unsigned* __restrict__ ei, long long ei_words,
                       const unsigned* __restrict__ bt, long long bt_words) {
    int b = blockIdx.x;
    if (b < INIT_PREPW_BLKS) {
        int idx = b * 256 + threadIdx.x;          // k'(128) x n(256)
        int kp = idx >> 8, n = idx & 255;
        const float* Ws[3] = {W1, W2, W3};
#pragma unroll
        for (int l = 0; l < 3; l++) {
            float x0 = Ws[l][(2 * kp) * DD + n];
            float x1 = Ws[l][(2 * kp + 1) * DD + n];
            uint32_t h = f2h(x0, x1);
            float2 back = h2f(h);
            uint32_t lo = f2h(x0 - back.x, x1 - back.y);
            g_WpH[l][kp * DD + n] = h;
            g_WpL[l][kp * DD + n] = lo;
        }
        return;
    }
    if (b < INIT_PREPW_BLKS + INIT_ZERO_BLKS) {
        int i = (b - INIT_PREPW_BLKS) * 256 + threadIdx.x;
        if (i < NN) g_degi[i] = 0;
        int j = i - NN;
        if (j >= 0 && j < GG * DD) g_pool[j] = 0.f;
        int k = j - GG * DD;
        if (k >= 0 && k < GG) g_cnt[k] = 0.f;
        return;
    }
    if (b < INIT_PREPW_BLKS + INIT_ZERO_BLKS + INIT_XCVT_BLKS) {
        int i = (b - INIT_PREPW_BLKS - INIT_ZERO_BLKS) * 256 + threadIdx.x;
        if (i < NN * 32) {
            int n = i >> 5, q = i & 31;            // q covers cols [q*8, q*8+8)
            const float* src = x + (long long)n * DD + q * 8;
            float4 v0 = *(const float4*)(src);
            float4 v1 = *(const float4*)(src + 4);
            uint4 o;
            o.x = f2h(v0.x, v0.y); o.y = f2h(v0.z, v0.w);
            o.z = f2h(v1.x, v1.y); o.w = f2h(v1.z, v1.w);
            *(uint4*)&xh[n * 128 + q * 4] = o;
        }
        return;
    }
    long long base = (long long)(b - INIT_PREPW_BLKS - INIT_ZERO_BLKS - INIT_XCVT_BLKS)
                     * 256 + threadIdx.x;
    long long i = 2 * base + 1;
    unsigned v0 = (i < ei_words) ? ei[i] : 0u;
    unsigned v1 = (i < bt_words) ? bt[i] : 0u;
#pragma unroll
    for (int o = 16; o > 0; o >>= 1) {
        v0 |= __shfl_xor_sync(0xffffffffu, v0, o);
        v1 |= __shfl_xor_sync(0xffffffffu, v1, o);
    }
    if ((threadIdx.x & 31) == 0) {
        if (v0) atomicOr(&g_flags[0], 1);
        if (v1) atomicOr(&g_flags[1], 1);
    }
}

__global__ void k_count(const void* __restrict__ ei, long long E) {
    long long e = (long long)blockIdx.x * blockDim.x + threadIdx.x;
    if (e >= E) return;
    int is32 = g_flags[0];
    long long d = fetch_idx(ei, E + e, is32);
    atomicAdd(&g_degi[d], 1);
}

__global__ void k_scan_dinv() {
    __shared__ int part[1024];
    const int CH = (NN + 1023) / 1024;
    int t = threadIdx.x;
    int beg = t * CH, end = min(beg + CH, NN);
    int s = 0;
    for (int i = beg; i < end; i++) {
        int d = g_degi[i];
        g_dinv[i] = rsqrtf((float)d + 1.0f);
        s += d;
    }
    part[t] = s;
    __syncthreads();
    for (int off = 1; off < 1024; off <<= 1) {
        int v = (t >= off) ? part[t - off] : 0;
        __syncthreads();
        part[t] += v;
        __syncthreads();
    }
    int excl = (t == 0) ? 0 : part[t - 1];
    for (int i = beg; i < end; i++) {
        g_rowptr[i] = excl;
        g_cursor[i] = excl;
        excl += g_degi[i];
    }
    if (t == 1023) g_rowptr[NN] = part[1023];
}

__global__ void k_fill(const void* __restrict__ ei, long long E) {
    long long e = (long long)blockIdx.x * blockDim.x + threadIdx.x;
    if (e >= E) return;
    int is32 = g_flags[0];
    int s = (int)fetch_idx(ei, e, is32);
    int d = (int)fetch_idx(ei, E + e, is32);
    int pos = atomicAdd(&g_cursor[d], 1);
    float w = g_dinv[s] * g_dinv[d];
    g_csr[pos] = make_uint2((uint32_t)s, __float_as_uint(w));
}

// ---------------- 2-term fp16 GEMM: C16 = A16 @ (Wh + Wl) ----------------------
// Block 128x128 (grid 391 x 2), 8 warps (2m x 4n), warp tile 64x32, BK=16.
// A fp16 exact (one plane, staging = pure copy); W split fp16 hi + fp16 lo.
#define APAD 12
#define BPAD 136
#define A_WORDS (2 * 128 * APAD)               // 3072 (one plane, 2 buffers)
#define B_WORDS (2 * 2 * 8 * BPAD)             // 4352
#define GEMM_SMEM ((A_WORDS + B_WORDS) * 4)    // 29696 bytes

#define AS(b, r, k)    sA[(((b) * 128 + (r)) * APAD) + (k)]
#define BS(b, h, k, n) sB[((((b) * 2 + (h)) * 8 + (k)) * BPAD) + (n)]

__global__ __launch_bounds__(256, 2) void k_gemm9(const uint32_t* __restrict__ A16,
                                                  const uint32_t* __restrict__ BH,
                                                  const uint32_t* __restrict__ BL,
                                                  uint32_t* __restrict__ C16, int M) {
    extern __shared__ uint32_t smem_dyn[];
    uint32_t* sA = smem_dyn;
    uint32_t* sB = smem_dyn + A_WORDS;

    int tid = threadIdx.x, wid = tid >> 5, lane = tid & 31;
    int g = lane >> 2, t = lane & 3;
    int wm = wid & 1, wn = wid >> 1;
    int bm = blockIdx.x * 128;
    int bn = blockIdx.y * 128;

    int a_row  = tid >> 1;                 // 0..127
    int a_half = tid & 1;                  // words [a_half*4, +4) of the 8-word chunk
    int b_kp   = tid >> 5;
    int b_col  = (tid & 31) * 4;

    int arow_c = bm + a_row < M ? bm + a_row : 0;
    bool a_ok = (bm + a_row) < M;
    const uint32_t* Aw = A16 + (long long)arow_c * 128 + a_half * 4;
    const uint4 zu4 = make_uint4(0, 0, 0, 0);

    float acc[4][4][4];
#pragma unroll
    for (int i = 0; i < 4; i++)
#pragma unroll
        for (int j = 0; j < 4; j++)
#pragma unroll
            for (int q = 0; q < 4; q++) acc[i][j][q] = 0.f;

    // prologue: stage chunk 0 into buffer 0 (A: pure copy)
    {
        uint4 va = a_ok ? *(const uint4*)(Aw) : zu4;
        *(uint4*)&AS(0, a_row, a_half * 4) = va;
        uint4 bh4 = *(const uint4*)(BH + (long long)b_kp * DD + bn + b_col);
        uint4 bl4 = *(const uint4*)(BL + (long long)b_kp * DD + bn + b_col);
        *(uint4*)&BS(0, 0, b_kp, b_col) = bh4;
        *(uint4*)&BS(0, 1, b_kp, b_col) = bl4;
    }
    __syncthreads();

    const int NSTEP = DD / 16;
    for (int k0 = 0; k0 < NSTEP; k0++) {
        int cur = k0 & 1, nxt = cur ^ 1;
        bool more = (k0 + 1) < NSTEP;

        uint4 va = zu4, pbh = zu4, pbl = zu4;
        if (more) {
            va = a_ok ? *(const uint4*)(Aw + (k0 + 1) * 8) : zu4;
            int kp = (k0 + 1) * 8 + b_kp;
            pbh = *(const uint4*)(BH + (long long)kp * DD + bn + b_col);
            pbl = *(const uint4*)(BL + (long long)kp * DD + bn + b_col);
        }

        uint32_t bh[4][2], bl[4][2];
#pragma unroll
        for (int j = 0; j < 4; j++) {
            int n = wn * 32 + 8 * j + g;
            bh[j][0] = BS(cur, 0, t, n);     bh[j][1] = BS(cur, 0, t + 4, n);
            bl[j][0] = BS(cur, 1, t, n);     bl[j][1] = BS(cur, 1, t + 4, n);
        }
#pragma unroll
        for (int i = 0; i < 4; i++) {
            int r = wm * 64 + i * 16;
            uint32_t ah[4];
            ah[0] = AS(cur, r + g, t);      ah[1] = AS(cur, r + g + 8, t);
            ah[2] = AS(cur, r + g, t + 4);  ah[3] = AS(cur, r + g + 8, t + 4);
#pragma unroll
            for (int j = 0; j < 4; j++) {
                mma16f(acc[i][j], ah, bh[j]);
                mma16f(acc[i][j], ah, bl[j]);
            }
        }

        if (more) {
            *(uint4*)&AS(nxt, a_row, a_half * 4) = va;
            *(uint4*)&BS(nxt, 0, b_kp, b_col) = pbh;
            *(uint4*)&BS(nxt, 1, b_kp, b_col) = pbl;
        }
        __syncthreads();
    }

    // epilogue: pack (col, col+1) fp32 pairs -> half2 word
#pragma unroll
    for (int i = 0; i < 4; i++)
#pragma unroll
        for (int j = 0; j < 4; j++) {
            int row0 = bm + wm * 64 + i * 16 + g;
            int widx = (bn >> 1) + wn * 16 + 4 * j + t;
            if (row0 < M)
                C16[(long long)row0 * 128 + widx] = f2h(acc[i][j][0], acc[i][j][1]);
            int row1 = row0 + 8;
            if (row1 < M)
                C16[(long long)row1 * 128 + widx] = f2h(acc[i][j][2], acc[i][j][3]);
        }
}

// -------- fused aggregate on fp16 rows: 1 warp/node, unroll x4 -----------------
__global__ __launch_bounds__(256) void k_aggregate_h(const uint32_t* __restrict__ tmp,
                                                     uint32_t* __restrict__ outh,
                                                     float* __restrict__ outf,
                                                     const float* __restrict__ bias,
                                                     int pack) {
    int node = (int)(((long long)blockIdx.x * blockDim.x + threadIdx.x) >> 5);
    int lane = threadIdx.x & 31;
    if (node >= NN) return;

    float a[8];
    {
        float di = g_dinv[node];
        float ws = di * di;
        uint4 v = *(const uint4*)(tmp + (long long)node * 128 + lane * 4);
        float2 f0 = h2f(v.x), f1 = h2f(v.y), f2 = h2f(v.z), f3 = h2f(v.w);
        a[0] = ws * f0.x; a[1] = ws * f0.y; a[2] = ws * f1.x; a[3] = ws * f1.y;
        a[4] = ws * f2.x; a[5] = ws * f2.y; a[6] = ws * f3.x; a[7] = ws * f3.y;
    }

    int p = g_rowptr[node], pe = g_rowptr[node + 1];
    for (; p + 4 <= pe; p += 4) {
        uint2 e0 = g_csr[p],     e1 = g_csr[p + 1];
        uint2 e2 = g_csr[p + 2], e3 = g_csr[p + 3];
        uint4 v0 = *(const uint4*)(tmp + (long long)e0.x * 128 + lane * 4);
        uint4 v1 = *(const uint4*)(tmp + (long long)e1.x * 128 + lane * 4);
        uint4 v2 = *(const uint4*)(tmp + (long long)e2.x * 128 + lane * 4);
        uint4 v3 = *(const uint4*)(tmp + (long long)e3.x * 128 + lane * 4);
        float w0 = __uint_as_float(e0.y), w1 = __uint_as_float(e1.y);
        float w2 = __uint_as_float(e2.y), w3 = __uint_as_float(e3.y);
        float2 f;
        f = h2f(v0.x); a[0] += w0 * f.x; a[1] += w0 * f.y;
        f = h2f(v0.y); a[2] += w0 * f.x; a[3] += w0 * f.y;
        f = h2f(v0.z); a[4] += w0 * f.x; a[5] += w0 * f.y;
        f = h2f(v0.w); a[6] += w0 * f.x; a[7] += w0 * f.y;
        f = h2f(v1.x); a[0] += w1 * f.x; a[1] += w1 * f.y;
        f = h2f(v1.y); a[2] += w1 * f.x; a[3] += w1 * f.y;
        f = h2f(v1.z); a[4] += w1 * f.x; a[5] += w1 * f.y;
        f = h2f(v1.w); a[6] += w1 * f.x; a[7] += w1 * f.y;
        f = h2f(v2.x); a[0] += w2 * f.x; a[1] += w2 * f.y;
        f = h2f(v2.y); a[2] += w2 * f.x; a[3] += w2 * f.y;
        f = h2f(v2.z); a[4] += w2 * f.x; a[5] += w2 * f.y;
        f = h2f(v2.w); a[6] += w2 * f.x; a[7] += w2 * f.y;
        f = h2f(v3.x); a[0] += w3 * f.x; a[1] += w3 * f.y;
        f = h2f(v3.y); a[2] += w3 * f.x; a[3] += w3 * f.y;
        f = h2f(v3.z); a[4] += w3 * f.x; a[5] += w3 * f.y;
        f = h2f(v3.w); a[6] += w3 * f.x; a[7] += w3 * f.y;
    }
    for (; p < pe; ++p) {
        uint2 e = g_csr[p];
        float w = __uint_as_float(e.y);
        uint4 v = *(const uint4*)(tmp + (long long)e.x * 128 + lane * 4);
        float2 f;
        f = h2f(v.x); a[0] += w * f.x; a[1] += w * f.y;
        f = h2f(v.y); a[2] += w * f.x; a[3] += w * f.y;
        f = h2f(v.z); a[4] += w * f.x; a[5] += w * f.y;
        f = h2f(v.w); a[6] += w * f.x; a[7] += w * f.y;
    }

    float4 b0 = *(const float4*)(bias + lane * 8);
    float4 b1 = *(const float4*)(bias + lane * 8 + 4);
    a[0] = fmaxf(a[0] + b0.x, 0.f); a[1] = fmaxf(a[1] + b0.y, 0.f);
    a[2] = fmaxf(a[2] + b0.z, 0.f); a[3] = fmaxf(a[3] + b0.w, 0.f);
    a[4] = fmaxf(a[4] + b1.x, 0.f); a[5] = fmaxf(a[5] + b1.y, 0.f);
    a[6] = fmaxf(a[6] + b1.z, 0.f); a[7] = fmaxf(a[7] + b1.w, 0.f);

    if (pack) {
        uint4 o;
        o.x = f2h(a[0], a[1]); o.y = f2h(a[2], a[3]);
        o.z = f2h(a[4], a[5]); o.w = f2h(a[6], a[7]);
        *(uint4*)&outh[(long long)node * 128 + lane * 4] = o;
    } else {
        float4 o0 = {a[0], a[1], a[2], a[3]};
        float4 o1 = {a[4], a[5], a[6], a[7]};
        *(float4*)(outf + (long long)node * DD + lane * 8) = o0;
        *(float4*)(outf + (long long)node * DD + lane * 8 + 4) = o1;
    }
}

// ---------------- pool (batch sorted) + fc ----------------
__global__ void k_pool2(const float* __restrict__ h, const void* __restrict__ batch) {
    int col = threadIdx.x;
    int n0 = blockIdx.x * 128;
    int n1 = min(n0 + 128, NN);
    int is32 = g_flags[1];
    int cur = (int)fetch_idx(batch, n0, is32);
    float acc = 0.f;
    int cnt = 0;
    for (int n = n0; n < n1; n++) {
        int gid = (int)fetch_idx(batch, n, is32);
        if (gid != cur) {
            atomicAdd(&g_pool[cur * DD + col], acc);
            if (col == 0) atomicAdd(&g_cnt[cur], (float)cnt);
            acc = 0.f; cnt = 0; cur = gid;
        }
        acc += h[(long long)n * DD + col];
        cnt++;
    }
    atomicAdd(&g_pool[cur * DD + col], acc);
    if (col == 0) atomicAdd(&g_cnt[cur], (float)cnt);
}

__global__ void k_fc(const float* __restrict__ Wfc, const float* __restrict__ bfc,
                     float* __restrict__ out) {
    int tt = blockIdx.x * blockDim.x + threadIdx.x;
    if (tt < 2 && blockIdx.x == 0) g_flags[tt] = 0;
    if (tt >= GG * DOUT) return;
    int g = tt >> 4, o = tt & 15;
    float inv = 1.0f / fmaxf(g_cnt[g], 1.0f);
    float acc = 0.f;
#pragma unroll 8
    for (int k = 0; k < DD; k++) acc += g_pool[g * DD + k] * Wfc[k * DOUT + o];
    out[tt] = acc * inv + bfc[o];
}

// ---------------- launch ----------------
extern "C" void kernel_launch(void* const* d_in, const int* in_sizes, int n_in,
                              void* d_out, int out_size) {
    const float* x     = (const float*)d_in[0];
    const void*  ei    = d_in[1];
    const void*  batch = d_in[2];
    const float* W1 = (const float*)d_in[3];  const float* b1 = (const float*)d_in[4];
    const float* W2 = (const float*)d_in[5];  const float* b2 = (const float*)d_in[6];
    const float* W3 = (const float*)d_in[7];  const float* b3 = (const float*)d_in[8];
    const float* Wfc = (const float*)d_in[9]; const float* bfc = (const float*)d_in[10];
    float* out = (float*)d_out;

    long long E = in_sizes[1] / 2;
    long long ei_words = (long long)in_sizes[1];
    long long bt_words = (long long)in_sizes[2];

    float *S0, *S1;
    uint32_t *WpH, *WpL;
    cudaGetSymbolAddress((void**)&S0, g_S0);
    cudaGetSymbolAddress((void**)&S1, g_S1);
    cudaGetSymbolAddress((void**)&WpH, g_WpH);
    cudaGetSymbolAddress((void**)&WpL, g_WpL);
    uint32_t* S0w = (uint32_t*)S0;
    uint32_t* S1w = (uint32_t*)S1;

    cudaFuncSetAttribute(k_gemm9, cudaFuncAttributeMaxDynamicSharedMemorySize,
                         GEMM_SMEM);

    dim3 gemm_grid((NN + 127) / 128, 2);
    int det_blocks = (int)((ei_words / 2 + 255) / 256);
    int init_blocks = INIT_PREPW_BLKS + INIT_ZERO_BLKS + INIT_XCVT_BLKS + det_blocks;
    const float* bs[3] = {b1, b2, b3};

    k_init<<<init_blocks, 256>>>(W1, W2, W3, x, S1w, (const unsigned*)ei, ei_words,
                                 (const unsigned*)batch, bt_words);            // 1
    k_count<<<(int)((E + 255) / 256), 256>>>(ei, E);                           // 2
    k_scan_dinv<<<1, 1024>>>();                                                // 3
    k_gemm9<<<gemm_grid, 256, GEMM_SMEM>>>(S1w, WpH, WpL, S0w, NN);            // 4 (profiled)
    k_fill<<<(int)((E + 255) / 256), 256>>>(ei, E);                            // 5
    k_aggregate_h<<<(NN * 32 + 255) / 256, 256>>>(S0w, S1w, S1, bs[0], 1);     // 6

    for (int l = 1; l < 3; l++) {
        k_gemm9<<<gemm_grid, 256, GEMM_SMEM>>>(S1w, WpH + (size_t)l * 128 * DD,
                                               WpL + (size_t)l * 128 * DD, S0w, NN);
        k_aggregate_h<<<(NN * 32 + 255) / 256, 256>>>(S0w, S1w, S1, bs[l],
                                                      l == 2 ? 0 : 1);
    }

    k_pool2<<<(NN + 127) / 128, 256>>>(S1, batch);
    k_fc<<<(GG * DOUT + 255) / 256, 256>>>(Wfc, bfc, out);
}